// round 11
// baseline (speedup 1.0000x reference)
#include <cuda_runtime.h>
#include <cuda_bf16.h>
#include <cstdint>
#include <math.h>

// Problem dims
#define BB 64
#define TT 512
#define DD 512
#define HH 512
#define NG 2048          // 4*H gate columns

// Recurrent partitioning: 128 CTAs = 4 batch-groups x 32 unit-CTAs
#define GCTA   128
#define NGRP   4
#define GRP_CTAS 32
#define ROWS_G 16        // batch rows per group
#define JW     16        // hidden units per CTA
#define GC     64        // gate cols per CTA
#define HP     520       // padded bf16 row stride for ldmatrix tiles
#define FSTRIDE 16       // flag padding: 16 u64 = 128 B between flags

// ---------------------------------------------------------------------------
// Device scratch (allocation-free per harness rules)
// ---------------------------------------------------------------------------
__device__ float g_xw[(size_t)TT * BB * NG];          // [m=t*64+r][2048] fp32 (bias incl.)
__device__ unsigned long long g_flags[NGRP * GRP_CTAS * FSTRIDE]; // padded flags
__device__ __nv_bfloat16 g_xhi[(size_t)TT * BB * DD]; // X split hi [32768,512]
__device__ __nv_bfloat16 g_xlo[(size_t)TT * BB * DD]; // X split lo
__device__ __nv_bfloat16 g_wthi[(size_t)NG * DD];     // Wx^T hi [2048,512]
__device__ __nv_bfloat16 g_wtlo[(size_t)NG * DD];     // Wx^T lo
__device__ __nv_bfloat16 g_hbf_hi[2][BB * HH];        // h split hi, [r][k], dbl-buf
__device__ __nv_bfloat16 g_hbf_lo[2][BB * HH];        // h split lo

__device__ __forceinline__ float sigf(float x) {
    return 1.0f / (1.0f + __expf(-x));
}

__device__ __forceinline__ uint32_t smem_u32(const void* p) {
    uint32_t a;
    asm("{ .reg .u64 t; cvta.to.shared.u64 t, %1; cvt.u32.u64 %0, t; }"
        : "=r"(a) : "l"(p));
    return a;
}

__device__ __forceinline__ void flag_release(unsigned long long* p,
                                             unsigned long long v) {
    asm volatile(
        "{ .reg .u64 a; cvta.to.global.u64 a, %0;"
        "  st.release.gpu.global.u64 [a], %1; }"
        :: "l"(p), "l"(v) : "memory");
}
__device__ __forceinline__ unsigned long long flag_acquire(
        const unsigned long long* p) {
    unsigned long long v;
    asm volatile(
        "{ .reg .u64 a; cvta.to.global.u64 a, %1;"
        "  ld.acquire.gpu.global.u64 %0, [a]; }"
        : "=l"(v) : "l"(p) : "memory");
    return v;
}

// ---------------------------------------------------------------------------
// mma.sync / ldmatrix / cp.async helpers (baseline PTX, plain sm_103 target)
// ---------------------------------------------------------------------------
__device__ __forceinline__ void ldsm_x4(uint32_t& r0, uint32_t& r1,
                                        uint32_t& r2, uint32_t& r3,
                                        uint32_t addr) {
    asm volatile("ldmatrix.sync.aligned.m8n8.x4.shared.b16 {%0,%1,%2,%3}, [%4];"
                 : "=r"(r0), "=r"(r1), "=r"(r2), "=r"(r3) : "r"(addr));
}
__device__ __forceinline__ void ldsm_x2(uint32_t& r0, uint32_t& r1,
                                        uint32_t addr) {
    asm volatile("ldmatrix.sync.aligned.m8n8.x2.shared.b16 {%0,%1}, [%2];"
                 : "=r"(r0), "=r"(r1) : "r"(addr));
}
__device__ __forceinline__ void mma16816(float* c, const uint32_t* a,
                                         const uint32_t* b) {
    asm volatile(
        "mma.sync.aligned.m16n8k16.row.col.f32.bf16.bf16.f32 "
        "{%0,%1,%2,%3}, {%4,%5,%6,%7}, {%8,%9}, {%0,%1,%2,%3};"
        : "+f"(c[0]), "+f"(c[1]), "+f"(c[2]), "+f"(c[3])
        : "r"(a[0]), "r"(a[1]), "r"(a[2]), "r"(a[3]), "r"(b[0]), "r"(b[1]));
}
#define CP_ASYNC16(dst_u32, src_ptr) \
    asm volatile("cp.async.cg.shared.global [%0], [%1], 16;" \
                 :: "r"(dst_u32), "l"(src_ptr))
#define CP_COMMIT() asm volatile("cp.async.commit_group;" ::: "memory")
#define CP_WAIT(N)  asm volatile("cp.async.wait_group %0;" :: "n"(N) : "memory")

// ---------------------------------------------------------------------------
// Kernel 0a: bf16 hi/lo split conversion of X and Wx^T. (unchanged)
// ---------------------------------------------------------------------------
__global__ void __launch_bounds__(256) conv_kernel(const float* __restrict__ x,
                                                   const float* __restrict__ W) {
    const size_t stride = (size_t)gridDim.x * blockDim.x;
    const size_t id0 = (size_t)blockIdx.x * blockDim.x + threadIdx.x;

    for (size_t i = id0; i < (size_t)TT * BB * DD; i += stride) {
        size_t m = i >> 9;
        int k = (int)(i & 511);
        int t = (int)(m >> 6);
        int r = (int)(m & 63);
        float v = x[(size_t)r * (TT * DD) + (size_t)t * DD + k];
        __nv_bfloat16 hi = __float2bfloat16(v);
        g_xhi[i] = hi;
        g_xlo[i] = __float2bfloat16(v - __bfloat162float(hi));
    }

    for (size_t i = id0; i < (size_t)NG * DD; i += stride) {
        int n = (int)(i & (NG - 1));
        int k = (int)(i >> 11);
        float v = W[(size_t)(HH + k) * NG + n];
        __nv_bfloat16 hi = __float2bfloat16(v);
        g_wthi[(size_t)n * DD + k] = hi;
        g_wtlo[(size_t)n * DD + k] = __float2bfloat16(v - __bfloat162float(hi));
    }
}

// ---------------------------------------------------------------------------
// Kernel 0b: per-replay state reset.
// ---------------------------------------------------------------------------
__global__ void __launch_bounds__(256) hinit_kernel() {
    int idx = blockIdx.x * blockDim.x + threadIdx.x;
    for (int i = idx; i < NGRP * GRP_CTAS * FSTRIDE;
         i += gridDim.x * blockDim.x)
        g_flags[i] = 0ULL;
    for (int i = idx; i < BB * HH; i += gridDim.x * blockDim.x) {
        g_hbf_hi[0][i] = __float2bfloat16(0.0f);
        g_hbf_lo[0][i] = __float2bfloat16(0.0f);
    }
}

// ---------------------------------------------------------------------------
// Kernel 1: bf16 3-term split GEMM via mma.sync, cp.async double-buffered.
// (unchanged from R10)
// ---------------------------------------------------------------------------
#define KP 40
#define XT (128 * KP)
#define XW_STAGE_B (4 * XT * 2)
#define XW_SMEM (2 * XW_STAGE_B)

__global__ void __launch_bounds__(256, 2) xw_mma(const float* __restrict__ bias) {
    extern __shared__ __align__(16) __nv_bfloat16 sbuf[];

    const int tid  = threadIdx.x;
    const int wid  = tid >> 5;
    const int lane = tid & 31;

    const int n0 = blockIdx.x * 128;
    const int m0 = blockIdx.y * 128;
    const int wm = (wid & 3) * 32;
    const int wn = (wid >> 2) * 64;

    const __nv_bfloat16* xh = g_xhi + (size_t)m0 * DD;
    const __nv_bfloat16* xl = g_xlo + (size_t)m0 * DD;
    const __nv_bfloat16* wh = g_wthi + (size_t)n0 * DD;
    const __nv_bfloat16* wl = g_wtlo + (size_t)n0 * DD;

    const uint32_t sb_u = smem_u32(sbuf);

    float cf[2][8][4];
#pragma unroll
    for (int mt = 0; mt < 2; ++mt)
#pragma unroll
        for (int nt = 0; nt < 8; ++nt)
#pragma unroll
            for (int i = 0; i < 4; ++i) cf[mt][nt][i] = 0.0f;

    const int srow = tid >> 2;
    const int sq   = (tid & 3) * 8;

    const int a_row = lane & 15;
    const int a_col = (lane >> 4) << 3;
    const int b_row = lane & 7;
    const int b_col = ((lane >> 3) & 1) << 3;

#define XW_ISSUE(K0, ST) do {                                                  \
        uint32_t sbase = sb_u + (uint32_t)(ST) * XW_STAGE_B;                   \
        _Pragma("unroll")                                                      \
        for (int i = 0; i < 2; ++i) {                                          \
            int row = srow + (i << 6);                                         \
            size_t go = (size_t)row * DD + (K0) + sq;                          \
            uint32_t so = sbase + (uint32_t)(row * KP + sq) * 2;               \
            CP_ASYNC16(so,              xh + go);                              \
            CP_ASYNC16(so + XT * 2,     xl + go);                              \
            CP_ASYNC16(so + 2 * XT * 2, wh + go);                              \
            CP_ASYNC16(so + 3 * XT * 2, wl + go);                              \
        }                                                                      \
        CP_COMMIT();                                                           \
    } while (0)

    XW_ISSUE(0, 0);

    for (int ci = 0; ci < 16; ++ci) {
        const int cur = ci & 1;
        if (ci < 15) {
            XW_ISSUE((ci + 1) * 32, cur ^ 1);
            CP_WAIT(1);
        } else {
            CP_WAIT(0);
        }
        __syncthreads();

        const uint32_t ah_u = sb_u + (uint32_t)cur * XW_STAGE_B;
        const uint32_t al_u = ah_u + XT * 2;
        const uint32_t bh_u = ah_u + 2 * XT * 2;
        const uint32_t bl_u = ah_u + 3 * XT * 2;

#pragma unroll
        for (int kk = 0; kk < 32; kk += 16) {
            uint32_t ah[2][4], al[2][4];
#pragma unroll
            for (int mt = 0; mt < 2; ++mt) {
                uint32_t off =
                    (uint32_t)(((wm + mt * 16 + a_row) * KP + kk + a_col) * 2);
                ldsm_x4(ah[mt][0], ah[mt][1], ah[mt][2], ah[mt][3], ah_u + off);
                ldsm_x4(al[mt][0], al[mt][1], al[mt][2], al[mt][3], al_u + off);
            }
#pragma unroll
            for (int nt = 0; nt < 8; ++nt) {
                uint32_t off =
                    (uint32_t)(((wn + nt * 8 + b_row) * KP + kk + b_col) * 2);
                uint32_t bh2[2], bl2[2];
                ldsm_x2(bh2[0], bh2[1], bh_u + off);
                ldsm_x2(bl2[0], bl2[1], bl_u + off);
#pragma unroll
                for (int mt = 0; mt < 2; ++mt) {
                    mma16816(cf[mt][nt], ah[mt], bh2);
                    mma16816(cf[mt][nt], ah[mt], bl2);
                    mma16816(cf[mt][nt], al[mt], bh2);
                }
            }
        }
        __syncthreads();
    }
#undef XW_ISSUE

    const int er = lane >> 2;
    const int ec = (lane & 3) << 1;
#pragma unroll
    for (int nt = 0; nt < 8; ++nt) {
        int coln = n0 + wn + nt * 8 + ec;
        float2 bv = *(const float2*)(bias + coln);
#pragma unroll
        for (int mt = 0; mt < 2; ++mt) {
            int rowm = m0 + wm + mt * 16 + er;
            float* d0 = g_xw + (size_t)rowm * NG + coln;
            float* d1 = g_xw + (size_t)(rowm + 8) * NG + coln;
            *(float2*)d0 = make_float2(cf[mt][nt][0] + bv.x, cf[mt][nt][1] + bv.y);
            *(float2*)d1 = make_float2(cf[mt][nt][2] + bv.x, cf[mt][nt][3] + bv.y);
        }
    }
}

// ---------------------------------------------------------------------------
// Kernel 2: persistent recurrent LSTM — flag-array barrier.
// 128 CTAs = 4 independent groups x 32 unit-CTAs (16 rows x 16 units each).
// Barrier: each CTA release-stores its own padded flag; warp 0 polls all 32
// group flags in parallel. out-store moved after the release.
// ---------------------------------------------------------------------------
#define LSTM_SMEM (160 * HP * 2 + 16 * 65 * 4 + 2 * 16 * 64 * 4 + 1024 + 1024)

__global__ void __launch_bounds__(256, 1) lstm_rec(const float* __restrict__ W,
                                                   float* __restrict__ out) {
    extern __shared__ __align__(16) char smraw[];
    __nv_bfloat16* shh = (__nv_bfloat16*)smraw;       // h hi [16][HP]
    __nv_bfloat16* shl = shh + 16 * HP;               // h lo
    __nv_bfloat16* swh = shl + 16 * HP;               // W_h hi [64][HP]
    __nv_bfloat16* swl = swh + 64 * HP;               // W_h lo
    float* sz   = (float*)(swl + 64 * HP);            // z tile [16][65]
    float* sxw  = sz + 16 * 65;                       // xw prefetch [2][16*64]
    float* shof = sxw + 2 * 16 * 64;                  // out f32 [16][16]
    __nv_bfloat16* shout = (__nv_bfloat16*)(shof + 256); // [2][256] hi/lo

    const int tid  = threadIdx.x;
    const int wid  = tid >> 5;
    const int lane = tid & 31;
    const int grp  = blockIdx.x >> 5;                 // batch group 0..3
    const int slot = blockIdx.x & 31;                 // CTA slot within group
    const int R0   = grp * ROWS_G;
    const int J0   = slot * JW;
    unsigned long long* myflag = &g_flags[(grp * GRP_CTAS + slot) * FSTRIDE];
    const unsigned long long* pollflag =
        &g_flags[(grp * GRP_CTAS + lane) * FSTRIDE];

    const uint32_t shh_u = smem_u32(shh);
    const uint32_t shl_u = smem_u32(shl);
    const uint32_t swh_u = smem_u32(swh);
    const uint32_t swl_u = smem_u32(swl);
    const uint32_t sxw_u = smem_u32(sxw);

    // xw prefetch ids: 16 rows x 64 local cols; 16B (4 floats) per thread
    const int xrow = tid >> 4;
    const int xn4  = tid & 15;
    const size_t xw_coloff = (size_t)((xn4 >> 2) << 9) + J0 + ((xn4 & 3) << 2);
    const uint32_t xw_soff = (uint32_t)(xrow * 64 + xn4 * 4) * 4;

    // Prologue: prefetch xw(t=0) into stage 0
    {
        const float* src = g_xw + ((size_t)(R0 + xrow)) * NG + xw_coloff;
        CP_ASYNC16(sxw_u + xw_soff, src);
        CP_COMMIT();
    }

    // Convert this CTA's W_h slice (64 gate cols) to bf16 hi/lo (once).
    for (int idx = tid; idx < GC * 512; idx += 256) {
        int n = idx & 63;
        int k = idx >> 6;
        float v = W[(size_t)k * NG + ((n >> 4) << 9) + J0 + (n & 15)];
        __nv_bfloat16 hi = __float2bfloat16(v);
        swh[n * HP + k] = hi;
        swl[n * HP + k] = __float2bfloat16(v - __bfloat162float(hi));
    }

    const int n0w = wid * 8;

    const int a_row = lane & 15;
    const int a_col = (lane >> 4) << 3;
    const int b_row = lane & 7;
    const int b_col = ((lane >> 3) & 1) << 3;

    const int er  = lane >> 2;
    const int ec2 = (lane & 3) << 1;
    const int gc  = n0w + ec2;

    const int gr = tid >> 4;
    const int gu = tid & 15;
    float cst = 0.0f;

    __syncthreads();

    for (int t = 0; t < TT; ++t) {
        const __nv_bfloat16* ghi = g_hbf_hi[t & 1] + (size_t)R0 * HH;
        const __nv_bfloat16* glo = g_hbf_lo[t & 1] + (size_t)R0 * HH;

        // Issue h chunks c0, c1 (K halves of 256)
#pragma unroll
        for (int cch = 0; cch < 2; ++cch) {
#pragma unroll
            for (int j = 0; j < 2; ++j) {
                int idx = tid + (j << 8);
                int row = idx >> 5;
                int seg = idx & 31;
                int eoff = row * HP + cch * 256 + seg * 8;
                int goff = (row << 9) + cch * 256 + seg * 8;
                CP_ASYNC16(shh_u + eoff * 2, ghi + goff);
                CP_ASYNC16(shl_u + eoff * 2, glo + goff);
            }
            CP_COMMIT();
        }
        // Prefetch xw(t+1)
        {
            int tn = (t + 1 < TT) ? t + 1 : TT - 1;
            const float* src =
                g_xw + ((size_t)tn * 64 + R0 + xrow) * NG + xw_coloff;
            CP_ASYNC16(sxw_u + ((((t + 1) & 1)) << 12) + xw_soff, src);
            CP_COMMIT();
        }

        // forces {xw(t), c0}; c1 + xw(t+1) may pend
        CP_WAIT(2);
        __syncthreads();

        // Accumulator init from smem xw stage
        const float* xs = sxw + ((t & 1) << 10) + er * 64 + gc;
        float2 x0 = *(const float2*)xs;
        float2 x1 = *(const float2*)(xs + 8 * 64);
        float chh[4] = {x0.x, x0.y, x1.x, x1.y};
        float chl[4] = {0.f, 0.f, 0.f, 0.f};
        float clh[4] = {0.f, 0.f, 0.f, 0.f};

#define LSTM_CHUNK(CCH)                                                        \
        {                                                                      \
            _Pragma("unroll")                                                  \
            for (int ks8 = 0; ks8 < 16; ++ks8) {                               \
                uint32_t aoff = (uint32_t)((a_row * HP +                       \
                                 (CCH) * 256 + ks8 * 16 + a_col) * 2);         \
                uint32_t boff = (uint32_t)(((n0w + b_row) * HP +               \
                                 (CCH) * 256 + ks8 * 16 + b_col) * 2);         \
                uint32_t ah[4], al[4], bh2[2], bl2[2];                         \
                ldsm_x4(ah[0], ah[1], ah[2], ah[3], shh_u + aoff);             \
                ldsm_x4(al[0], al[1], al[2], al[3], shl_u + aoff);             \
                ldsm_x2(bh2[0], bh2[1], swh_u + boff);                         \
                ldsm_x2(bl2[0], bl2[1], swl_u + boff);                         \
                mma16816(chh, ah, bh2);                                        \
                mma16816(chl, ah, bl2);                                        \
                mma16816(clh, al, bh2);                                        \
            }                                                                  \
        }
        LSTM_CHUNK(0)
        CP_WAIT(1);          // forces c1 (xw(t+1) may pend)
        __syncthreads();
        LSTM_CHUNK(1)
#undef LSTM_CHUNK

        // z -> smem z tile [16][65]
        sz[er * 65 + gc]           = chh[0] + chl[0] + clh[0];
        sz[er * 65 + gc + 1]       = chh[1] + chl[1] + clh[1];
        sz[(er + 8) * 65 + gc]     = chh[2] + chl[2] + clh[2];
        sz[(er + 8) * 65 + gc + 1] = chh[3] + chl[3] + clh[3];
        __syncthreads();

        // Gate math: local cols [0..15]=f, [16..31]=i, [32..47]=o, [48..63]=c_bar
        float zf = sz[gr * 65 + gu];
        float zi = sz[gr * 65 + 16 + gu];
        float zo = sz[gr * 65 + 32 + gu];
        float zc = sz[gr * 65 + 48 + gu];
        cst = sigf(zf) * cst + sigf(zi) * zc;
        float h = sigf(zo) * cst;

        // Stage outputs for coalesced stores
        shof[gr * 16 + gu] = h;
        __nv_bfloat16 hhi = __float2bfloat16(h);
        shout[gr * 16 + gu]       = hhi;
        shout[256 + gr * 16 + gu] = __float2bfloat16(h - __bfloat162float(hhi));
        __syncthreads();

        // h state stores FIRST (they gate the other CTAs)
        if (tid < 32) {                    // h hi: 16 rows x 32B
            int rr = tid >> 1, hf = tid & 1;
            *(uint4*)(g_hbf_hi[(t + 1) & 1] + ((size_t)(R0 + rr) << 9) + J0 + hf * 8)
                = *(uint4*)&shout[rr * 16 + hf * 8];
        } else if (tid < 64) {             // h lo
            int i = tid - 32, rr = i >> 1, hf = i & 1;
            *(uint4*)(g_hbf_lo[(t + 1) & 1] + ((size_t)(R0 + rr) << 9) + J0 + hf * 8)
                = *(uint4*)&shout[256 + rr * 16 + hf * 8];
        }
        __syncthreads();                   // h stores ordered before release

        // Release own flag (parallel across CTAs; padded, no contention)
        if (tid == 0) flag_release(myflag, (unsigned long long)(t + 1));

        // out-store: off the critical path (after release)
        if (tid >= 64 && tid < 128) {
            int i = tid - 64, rr = i >> 2, q = i & 3;
            *(float4*)(out + (size_t)(R0 + rr) * (TT * HH) + (size_t)t * HH +
                       J0 + q * 4) = *(float4*)&shof[rr * 16 + q * 4];
        }

        // Wait: warp 0 polls all 32 group flags in parallel (1 flag/lane)
        if (wid == 0) {
            while (flag_acquire(pollflag) < (unsigned long long)(t + 1)) { }
        }
        __syncthreads();
    }
}

// ---------------------------------------------------------------------------
extern "C" void kernel_launch(void* const* d_in, const int* in_sizes, int n_in,
                              void* d_out, int out_size) {
    const float* x = (const float*)d_in[0];   // [64, 512, 512]
    const float* W = (const float*)d_in[1];   // [1024, 2048]
    const float* b = (const float*)d_in[2];   // [2048]
    float* out = (float*)d_out;               // [64, 512, 512]

    conv_kernel<<<1024, 256>>>(x, W);
    hinit_kernel<<<32, 256>>>();

    cudaFuncSetAttribute(xw_mma, cudaFuncAttributeMaxDynamicSharedMemorySize,
                         XW_SMEM);
    dim3 g1(NG / 128, (TT * BB) / 128);       // (16, 256)
    xw_mma<<<g1, 256, XW_SMEM>>>(b);

    cudaFuncSetAttribute(lstm_rec, cudaFuncAttributeMaxDynamicSharedMemorySize,
                         LSTM_SMEM);
    lstm_rec<<<GCTA, 256, LSTM_SMEM>>>(W, out);
}

// round 12
// speedup vs baseline: 1.2463x; 1.2463x over previous
#include <cuda_runtime.h>
#include <cuda_bf16.h>
#include <cuda_fp16.h>
#include <cstdint>
#include <math.h>

// Problem dims
#define BB 64
#define TT 512
#define DD 512
#define HH 512
#define NG 2048          // 4*H gate columns

// Recurrent partitioning: 128 CTAs = 4 batch-groups x 32 unit-CTAs
#define GCTA   128
#define NGRP   4
#define GRP_CTAS 32
#define ROWS_G 16        // batch rows per group
#define JW     16        // hidden units per CTA
#define GC     64        // gate cols per CTA
#define HP     520       // padded row stride (elements) for ldmatrix tiles

// ---------------------------------------------------------------------------
// Device scratch (allocation-free per harness rules)
// ---------------------------------------------------------------------------
__device__ float g_xw[(size_t)TT * BB * NG];          // [m=t*64+r][2048] fp32 (bias incl.)
__device__ unsigned long long g_bars[NGRP * 32];      // per-group counters, 256B apart
__device__ __nv_bfloat16 g_xhi[(size_t)TT * BB * DD]; // X split hi [32768,512]
__device__ __nv_bfloat16 g_xlo[(size_t)TT * BB * DD]; // X split lo
__device__ __nv_bfloat16 g_wthi[(size_t)NG * DD];     // Wx^T hi [2048,512]
__device__ __nv_bfloat16 g_wtlo[(size_t)NG * DD];     // Wx^T lo
__device__ __half g_hf16[2][BB * HH];                 // h state fp16, [r][k], dbl-buf

__device__ __forceinline__ float sigf(float x) {
    return 1.0f / (1.0f + __expf(-x));
}

__device__ __forceinline__ uint32_t smem_u32(const void* p) {
    uint32_t a;
    asm("{ .reg .u64 t; cvta.to.shared.u64 t, %1; cvt.u32.u64 %0, t; }"
        : "=r"(a) : "l"(p));
    return a;
}

__device__ __forceinline__ void bar_arrive_release(unsigned long long* ctr) {
    asm volatile(
        "{ .reg .u64 a; cvta.to.global.u64 a, %0;"
        "  red.release.gpu.global.add.u64 [a], %1; }"
        :: "l"(ctr), "l"(1ULL) : "memory");
}
__device__ __forceinline__ unsigned long long bar_ld_acquire(
        unsigned long long* ctr) {
    unsigned long long v;
    asm volatile(
        "{ .reg .u64 a; cvta.to.global.u64 a, %1;"
        "  ld.acquire.gpu.global.u64 %0, [a]; }"
        : "=l"(v) : "l"(ctr) : "memory");
    return v;
}

// ---------------------------------------------------------------------------
// mma.sync / ldmatrix / cp.async helpers (baseline PTX, plain sm_103 target)
// ---------------------------------------------------------------------------
__device__ __forceinline__ void ldsm_x4(uint32_t& r0, uint32_t& r1,
                                        uint32_t& r2, uint32_t& r3,
                                        uint32_t addr) {
    asm volatile("ldmatrix.sync.aligned.m8n8.x4.shared.b16 {%0,%1,%2,%3}, [%4];"
                 : "=r"(r0), "=r"(r1), "=r"(r2), "=r"(r3) : "r"(addr));
}
__device__ __forceinline__ void ldsm_x2(uint32_t& r0, uint32_t& r1,
                                        uint32_t addr) {
    asm volatile("ldmatrix.sync.aligned.m8n8.x2.shared.b16 {%0,%1}, [%2];"
                 : "=r"(r0), "=r"(r1) : "r"(addr));
}
__device__ __forceinline__ void mma16816(float* c, const uint32_t* a,
                                         const uint32_t* b) {
    asm volatile(
        "mma.sync.aligned.m16n8k16.row.col.f32.bf16.bf16.f32 "
        "{%0,%1,%2,%3}, {%4,%5,%6,%7}, {%8,%9}, {%0,%1,%2,%3};"
        : "+f"(c[0]), "+f"(c[1]), "+f"(c[2]), "+f"(c[3])
        : "r"(a[0]), "r"(a[1]), "r"(a[2]), "r"(a[3]), "r"(b[0]), "r"(b[1]));
}
__device__ __forceinline__ void mma16816f(float* c, const uint32_t* a,
                                          const uint32_t* b) {
    asm volatile(
        "mma.sync.aligned.m16n8k16.row.col.f32.f16.f16.f32 "
        "{%0,%1,%2,%3}, {%4,%5,%6,%7}, {%8,%9}, {%0,%1,%2,%3};"
        : "+f"(c[0]), "+f"(c[1]), "+f"(c[2]), "+f"(c[3])
        : "r"(a[0]), "r"(a[1]), "r"(a[2]), "r"(a[3]), "r"(b[0]), "r"(b[1]));
}
#define CP_ASYNC16(dst_u32, src_ptr) \
    asm volatile("cp.async.cg.shared.global [%0], [%1], 16;" \
                 :: "r"(dst_u32), "l"(src_ptr))
#define CP_COMMIT() asm volatile("cp.async.commit_group;" ::: "memory")
#define CP_WAIT(N)  asm volatile("cp.async.wait_group %0;" :: "n"(N) : "memory")

// ---------------------------------------------------------------------------
// Kernel 0a: bf16 hi/lo split conversion of X and Wx^T. (unchanged)
// ---------------------------------------------------------------------------
__global__ void __launch_bounds__(256) conv_kernel(const float* __restrict__ x,
                                                   const float* __restrict__ W) {
    const size_t stride = (size_t)gridDim.x * blockDim.x;
    const size_t id0 = (size_t)blockIdx.x * blockDim.x + threadIdx.x;

    for (size_t i = id0; i < (size_t)TT * BB * DD; i += stride) {
        size_t m = i >> 9;
        int k = (int)(i & 511);
        int t = (int)(m >> 6);
        int r = (int)(m & 63);
        float v = x[(size_t)r * (TT * DD) + (size_t)t * DD + k];
        __nv_bfloat16 hi = __float2bfloat16(v);
        g_xhi[i] = hi;
        g_xlo[i] = __float2bfloat16(v - __bfloat162float(hi));
    }

    for (size_t i = id0; i < (size_t)NG * DD; i += stride) {
        int n = (int)(i & (NG - 1));
        int k = (int)(i >> 11);
        float v = W[(size_t)(HH + k) * NG + n];
        __nv_bfloat16 hi = __float2bfloat16(v);
        g_wthi[(size_t)n * DD + k] = hi;
        g_wtlo[(size_t)n * DD + k] = __float2bfloat16(v - __bfloat162float(hi));
    }
}

// ---------------------------------------------------------------------------
// Kernel 0b: per-replay state reset.
// ---------------------------------------------------------------------------
__global__ void __launch_bounds__(256) hinit_kernel() {
    int idx = blockIdx.x * blockDim.x + threadIdx.x;
    if (idx < NGRP * 32) g_bars[idx] = 0ULL;
    for (int i = idx; i < BB * HH; i += gridDim.x * blockDim.x)
        g_hf16[0][i] = __float2half(0.0f);
}

// ---------------------------------------------------------------------------
// Kernel 1: bf16 3-term split GEMM via mma.sync, cp.async double-buffered.
// (unchanged from R10)
// ---------------------------------------------------------------------------
#define KP 40
#define XT (128 * KP)
#define XW_STAGE_B (4 * XT * 2)
#define XW_SMEM (2 * XW_STAGE_B)

__global__ void __launch_bounds__(256, 2) xw_mma(const float* __restrict__ bias) {
    extern __shared__ __align__(16) __nv_bfloat16 sbuf[];

    const int tid  = threadIdx.x;
    const int wid  = tid >> 5;
    const int lane = tid & 31;

    const int n0 = blockIdx.x * 128;
    const int m0 = blockIdx.y * 128;
    const int wm = (wid & 3) * 32;
    const int wn = (wid >> 2) * 64;

    const __nv_bfloat16* xh = g_xhi + (size_t)m0 * DD;
    const __nv_bfloat16* xl = g_xlo + (size_t)m0 * DD;
    const __nv_bfloat16* wh = g_wthi + (size_t)n0 * DD;
    const __nv_bfloat16* wl = g_wtlo + (size_t)n0 * DD;

    const uint32_t sb_u = smem_u32(sbuf);

    float cf[2][8][4];
#pragma unroll
    for (int mt = 0; mt < 2; ++mt)
#pragma unroll
        for (int nt = 0; nt < 8; ++nt)
#pragma unroll
            for (int i = 0; i < 4; ++i) cf[mt][nt][i] = 0.0f;

    const int srow = tid >> 2;
    const int sq   = (tid & 3) * 8;

    const int a_row = lane & 15;
    const int a_col = (lane >> 4) << 3;
    const int b_row = lane & 7;
    const int b_col = ((lane >> 3) & 1) << 3;

#define XW_ISSUE(K0, ST) do {                                                  \
        uint32_t sbase = sb_u + (uint32_t)(ST) * XW_STAGE_B;                   \
        _Pragma("unroll")                                                      \
        for (int i = 0; i < 2; ++i) {                                          \
            int row = srow + (i << 6);                                         \
            size_t go = (size_t)row * DD + (K0) + sq;                          \
            uint32_t so = sbase + (uint32_t)(row * KP + sq) * 2;               \
            CP_ASYNC16(so,              xh + go);                              \
            CP_ASYNC16(so + XT * 2,     xl + go);                              \
            CP_ASYNC16(so + 2 * XT * 2, wh + go);                              \
            CP_ASYNC16(so + 3 * XT * 2, wl + go);                              \
        }                                                                      \
        CP_COMMIT();                                                           \
    } while (0)

    XW_ISSUE(0, 0);

    for (int ci = 0; ci < 16; ++ci) {
        const int cur = ci & 1;
        if (ci < 15) {
            XW_ISSUE((ci + 1) * 32, cur ^ 1);
            CP_WAIT(1);
        } else {
            CP_WAIT(0);
        }
        __syncthreads();

        const uint32_t ah_u = sb_u + (uint32_t)cur * XW_STAGE_B;
        const uint32_t al_u = ah_u + XT * 2;
        const uint32_t bh_u = ah_u + 2 * XT * 2;
        const uint32_t bl_u = ah_u + 3 * XT * 2;

#pragma unroll
        for (int kk = 0; kk < 32; kk += 16) {
            uint32_t ah[2][4], al[2][4];
#pragma unroll
            for (int mt = 0; mt < 2; ++mt) {
                uint32_t off =
                    (uint32_t)(((wm + mt * 16 + a_row) * KP + kk + a_col) * 2);
                ldsm_x4(ah[mt][0], ah[mt][1], ah[mt][2], ah[mt][3], ah_u + off);
                ldsm_x4(al[mt][0], al[mt][1], al[mt][2], al[mt][3], al_u + off);
            }
#pragma unroll
            for (int nt = 0; nt < 8; ++nt) {
                uint32_t off =
                    (uint32_t)(((wn + nt * 8 + b_row) * KP + kk + b_col) * 2);
                uint32_t bh2[2], bl2[2];
                ldsm_x2(bh2[0], bh2[1], bh_u + off);
                ldsm_x2(bl2[0], bl2[1], bl_u + off);
#pragma unroll
                for (int mt = 0; mt < 2; ++mt) {
                    mma16816(cf[mt][nt], ah[mt], bh2);
                    mma16816(cf[mt][nt], ah[mt], bl2);
                    mma16816(cf[mt][nt], al[mt], bh2);
                }
            }
        }
        __syncthreads();
    }
#undef XW_ISSUE

    const int er = lane >> 2;
    const int ec = (lane & 3) << 1;
#pragma unroll
    for (int nt = 0; nt < 8; ++nt) {
        int coln = n0 + wn + nt * 8 + ec;
        float2 bv = *(const float2*)(bias + coln);
#pragma unroll
        for (int mt = 0; mt < 2; ++mt) {
            int rowm = m0 + wm + mt * 16 + er;
            float* d0 = g_xw + (size_t)rowm * NG + coln;
            float* d1 = g_xw + (size_t)(rowm + 8) * NG + coln;
            *(float2*)d0 = make_float2(cf[mt][nt][0] + bv.x, cf[mt][nt][1] + bv.y);
            *(float2*)d1 = make_float2(cf[mt][nt][2] + bv.x, cf[mt][nt][3] + bv.y);
        }
    }
}

// ---------------------------------------------------------------------------
// Kernel 2: persistent recurrent LSTM — fp16 h, fp16-split weights.
// 128 CTAs = 4 groups x 32 unit-CTAs (16 rows x 16 units). Per k16-step:
// 1 ldsm_x4 (h fp16) + 2 ldsm_x2 (Wh hi/lo fp16) + 2 MMA (A*Bh + A*Bl).
// Counter barrier (R10); out-store after arrive.
// ---------------------------------------------------------------------------
#define LSTM_SMEM ((16 + 128) * HP * 2 + 16 * 65 * 4 + 2 * 16 * 64 * 4 + 1024 + 512)

__global__ void __launch_bounds__(256, 1) lstm_rec(const float* __restrict__ W,
                                                   float* __restrict__ out) {
    extern __shared__ __align__(16) char smraw[];
    __half* shh = (__half*)smraw;                     // h fp16 [16][HP]
    __half* swh = shh + 16 * HP;                      // W_h hi fp16 [64][HP]
    __half* swl = swh + 64 * HP;                      // W_h lo fp16
    float* sz   = (float*)(swl + 64 * HP);            // z tile [16][65]
    float* sxw  = sz + 16 * 65;                       // xw prefetch [2][16*64]
    float* shof = sxw + 2 * 16 * 64;                  // out f32 [16][16]
    __half* shout = (__half*)(shof + 256);            // h fp16 staging [256]

    const int tid  = threadIdx.x;
    const int wid  = tid >> 5;
    const int lane = tid & 31;
    const int grp  = blockIdx.x >> 5;                 // batch group 0..3
    const int slot = blockIdx.x & 31;
    const int R0   = grp * ROWS_G;
    const int J0   = slot * JW;
    unsigned long long* bar = &g_bars[grp * 32];

    const uint32_t shh_u = smem_u32(shh);
    const uint32_t swh_u = smem_u32(swh);
    const uint32_t swl_u = smem_u32(swl);
    const uint32_t sxw_u = smem_u32(sxw);

    // xw prefetch ids: 16 rows x 64 local cols; 16B (4 floats) per thread
    const int xrow = tid >> 4;
    const int xn4  = tid & 15;
    const size_t xw_coloff = (size_t)((xn4 >> 2) << 9) + J0 + ((xn4 & 3) << 2);
    const uint32_t xw_soff = (uint32_t)(xrow * 64 + xn4 * 4) * 4;

    // Prologue: prefetch xw(t=0) into stage 0
    {
        const float* src = g_xw + ((size_t)(R0 + xrow)) * NG + xw_coloff;
        CP_ASYNC16(sxw_u + xw_soff, src);
        CP_COMMIT();
    }

    // Convert this CTA's W_h slice (64 gate cols) to fp16 hi/lo (once).
    for (int idx = tid; idx < GC * 512; idx += 256) {
        int n = idx & 63;
        int k = idx >> 6;
        float v = W[(size_t)k * NG + ((n >> 4) << 9) + J0 + (n & 15)];
        __half hi = __float2half(v);
        swh[n * HP + k] = hi;
        swl[n * HP + k] = __float2half(v - __half2float(hi));
    }

    const int n0w = wid * 8;

    const int a_row = lane & 15;
    const int a_col = (lane >> 4) << 3;
    const int b_row = lane & 7;
    const int b_col = ((lane >> 3) & 1) << 3;

    const int er  = lane >> 2;
    const int ec2 = (lane & 3) << 1;
    const int gc  = n0w + ec2;

    const int gr = tid >> 4;
    const int gu = tid & 15;
    float cst = 0.0f;

    __syncthreads();

    for (int t = 0; t < TT; ++t) {
        const __half* gh = g_hf16[t & 1] + (size_t)R0 * HH;

        // Issue h chunks c0, c1 (K halves of 256): 2 x 16B per thread each
#pragma unroll
        for (int cch = 0; cch < 2; ++cch) {
            {
                int row = tid >> 4;            // 0..15
                int seg = tid & 15;            // 16 x 16B = 256 fp16 per row? no:
            }
            // 16 rows x 256 cols fp16 = 8192 B = 512 x 16B; 2 per thread
#pragma unroll
            for (int j = 0; j < 2; ++j) {
                int idx = tid + (j << 8);
                int row = idx >> 5;            // 0..15
                int seg = idx & 31;            // 32 x 8-elem segs
                int eoff = row * HP + cch * 256 + seg * 8;
                int goff = (row << 9) + cch * 256 + seg * 8;
                CP_ASYNC16(shh_u + eoff * 2, gh + goff);
            }
            CP_COMMIT();
        }
        // Prefetch xw(t+1)
        {
            int tn = (t + 1 < TT) ? t + 1 : TT - 1;
            const float* src =
                g_xw + ((size_t)tn * 64 + R0 + xrow) * NG + xw_coloff;
            CP_ASYNC16(sxw_u + ((((t + 1) & 1)) << 12) + xw_soff, src);
            CP_COMMIT();
        }

        // forces {xw(t), c0}; c1 + xw(t+1) may pend
        CP_WAIT(2);
        __syncthreads();

        // Accumulator init from smem xw stage; 2 independent chains
        const float* xs = sxw + ((t & 1) << 10) + er * 64 + gc;
        float2 x0 = *(const float2*)xs;
        float2 x1 = *(const float2*)(xs + 8 * 64);
        float ch[4] = {x0.x, x0.y, x1.x, x1.y};
        float cl[4] = {0.f, 0.f, 0.f, 0.f};

#define LSTM_CHUNK(CCH)                                                        \
        {                                                                      \
            _Pragma("unroll")                                                  \
            for (int ks8 = 0; ks8 < 16; ++ks8) {                               \
                uint32_t aoff = (uint32_t)((a_row * HP +                       \
                                 (CCH) * 256 + ks8 * 16 + a_col) * 2);         \
                uint32_t boff = (uint32_t)(((n0w + b_row) * HP +               \
                                 (CCH) * 256 + ks8 * 16 + b_col) * 2);         \
                uint32_t ah[4], bh2[2], bl2[2];                                \
                ldsm_x4(ah[0], ah[1], ah[2], ah[3], shh_u + aoff);             \
                ldsm_x2(bh2[0], bh2[1], swh_u + boff);                         \
                ldsm_x2(bl2[0], bl2[1], swl_u + boff);                         \
                mma16816f(ch, ah, bh2);                                        \
                mma16816f(cl, ah, bl2);                                        \
            }                                                                  \
        }
        LSTM_CHUNK(0)
        CP_WAIT(1);          // forces c1 (xw(t+1) may pend)
        __syncthreads();
        LSTM_CHUNK(1)
#undef LSTM_CHUNK

        // z -> smem z tile [16][65]
        sz[er * 65 + gc]           = ch[0] + cl[0];
        sz[er * 65 + gc + 1]       = ch[1] + cl[1];
        sz[(er + 8) * 65 + gc]     = ch[2] + cl[2];
        sz[(er + 8) * 65 + gc + 1] = ch[3] + cl[3];
        __syncthreads();

        // Gate math: local cols [0..15]=f, [16..31]=i, [32..47]=o, [48..63]=c_bar
        float zf = sz[gr * 65 + gu];
        float zi = sz[gr * 65 + 16 + gu];
        float zo = sz[gr * 65 + 32 + gu];
        float zc = sz[gr * 65 + 48 + gu];
        cst = sigf(zf) * cst + sigf(zi) * zc;
        float h = sigf(zo) * cst;

        // Stage outputs for coalesced stores
        shof[gr * 16 + gu]  = h;
        shout[gr * 16 + gu] = __float2half(h);
        __syncthreads();

        // h state stores FIRST (they gate the other CTAs): 16 rows x 32B
        if (tid < 32) {
            int rr = tid >> 1, hf = tid & 1;
            *(uint4*)(g_hf16[(t + 1) & 1] + ((size_t)(R0 + rr) << 9) + J0 + hf * 8)
                = *(uint4*)&shout[rr * 16 + hf * 8];
        }
        __syncthreads();                   // h stores ordered before release

        if (tid == 0) bar_arrive_release(bar);

        // out-store: off the critical path (after arrive)
        if (tid >= 64 && tid < 128) {
            int i = tid - 64, rr = i >> 2, q = i & 3;
            *(float4*)(out + (size_t)(R0 + rr) * (TT * HH) + (size_t)t * HH +
                       J0 + q * 4) = *(float4*)&shof[rr * 16 + q * 4];
        }

        // Wait: single-counter poll (R10 pattern — flag array regressed)
        if (tid == 0) {
            unsigned long long target = (unsigned long long)(t + 1) * GRP_CTAS;
            while (bar_ld_acquire(bar) < target) { }
        }
        __syncthreads();
    }
}

// ---------------------------------------------------------------------------
extern "C" void kernel_launch(void* const* d_in, const int* in_sizes, int n_in,
                              void* d_out, int out_size) {
    const float* x = (const float*)d_in[0];   // [64, 512, 512]
    const float* W = (const float*)d_in[1];   // [1024, 2048]
    const float* b = (const float*)d_in[2];   // [2048]
    float* out = (float*)d_out;               // [64, 512, 512]

    conv_kernel<<<1024, 256>>>(x, W);
    hinit_kernel<<<32, 256>>>();

    cudaFuncSetAttribute(xw_mma, cudaFuncAttributeMaxDynamicSharedMemorySize,
                         XW_SMEM);
    dim3 g1(NG / 128, (TT * BB) / 128);       // (16, 256)
    xw_mma<<<g1, 256, XW_SMEM>>>(b);

    cudaFuncSetAttribute(lstm_rec, cudaFuncAttributeMaxDynamicSharedMemorySize,
                         LSTM_SMEM);
    lstm_rec<<<GCTA, 256, LSTM_SMEM>>>(W, out);
}

// round 13
// speedup vs baseline: 1.4037x; 1.1263x over previous
#include <cuda_runtime.h>
#include <cuda_bf16.h>
#include <cuda_fp16.h>
#include <cstdint>
#include <math.h>

// Problem dims
#define BB 64
#define TT 512
#define DD 512
#define HH 512
#define NG 2048          // 4*H gate columns

// Recurrent partitioning: 128 CTAs = 4 batch-groups x 32 unit-CTAs
#define GCTA   128
#define NGRP   4
#define GRP_CTAS 32
#define ROWS_G 16        // batch rows per group
#define JW     16        // hidden units per CTA
#define GC     64        // gate cols per CTA
#define HP     520       // padded row stride (elements) for ldmatrix tiles

// ---------------------------------------------------------------------------
// Device scratch (allocation-free per harness rules)
// ---------------------------------------------------------------------------
__device__ float g_xw[(size_t)TT * BB * NG];          // [m=t*64+r][2048] fp32 (bias incl.)
__device__ unsigned long long g_bars[NGRP * 32];      // per-group counters, 256B apart
__device__ __nv_bfloat16 g_xhi[(size_t)TT * BB * DD]; // X split hi [32768,512]
__device__ __nv_bfloat16 g_xlo[(size_t)TT * BB * DD]; // X split lo
__device__ __nv_bfloat16 g_wthi[(size_t)NG * DD];     // Wx^T hi [2048,512]
__device__ __nv_bfloat16 g_wtlo[(size_t)NG * DD];     // Wx^T lo
__device__ __half g_hf16[2][BB * HH];                 // h state fp16, [r][k], dbl-buf

__device__ __forceinline__ float sigf(float x) {
    return 1.0f / (1.0f + __expf(-x));
}

__device__ __forceinline__ uint32_t smem_u32(const void* p) {
    uint32_t a;
    asm("{ .reg .u64 t; cvta.to.shared.u64 t, %1; cvt.u32.u64 %0, t; }"
        : "=r"(a) : "l"(p));
    return a;
}

__device__ __forceinline__ void bar_arrive_release(unsigned long long* ctr) {
    asm volatile(
        "{ .reg .u64 a; cvta.to.global.u64 a, %0;"
        "  red.release.gpu.global.add.u64 [a], %1; }"
        :: "l"(ctr), "l"(1ULL) : "memory");
}
__device__ __forceinline__ unsigned long long bar_ld_acquire(
        unsigned long long* ctr) {
    unsigned long long v;
    asm volatile(
        "{ .reg .u64 a; cvta.to.global.u64 a, %1;"
        "  ld.acquire.gpu.global.u64 %0, [a]; }"
        : "=l"(v) : "l"(ctr) : "memory");
    return v;
}

// ---------------------------------------------------------------------------
// mma.sync / ldmatrix / cp.async helpers (baseline PTX, plain sm_103 target)
// ---------------------------------------------------------------------------
__device__ __forceinline__ void ldsm_x4(uint32_t& r0, uint32_t& r1,
                                        uint32_t& r2, uint32_t& r3,
                                        uint32_t addr) {
    asm volatile("ldmatrix.sync.aligned.m8n8.x4.shared.b16 {%0,%1,%2,%3}, [%4];"
                 : "=r"(r0), "=r"(r1), "=r"(r2), "=r"(r3) : "r"(addr));
}
__device__ __forceinline__ void ldsm_x2(uint32_t& r0, uint32_t& r1,
                                        uint32_t addr) {
    asm volatile("ldmatrix.sync.aligned.m8n8.x2.shared.b16 {%0,%1}, [%2];"
                 : "=r"(r0), "=r"(r1) : "r"(addr));
}
__device__ __forceinline__ void mma16816(float* c, const uint32_t* a,
                                         const uint32_t* b) {
    asm volatile(
        "mma.sync.aligned.m16n8k16.row.col.f32.bf16.bf16.f32 "
        "{%0,%1,%2,%3}, {%4,%5,%6,%7}, {%8,%9}, {%0,%1,%2,%3};"
        : "+f"(c[0]), "+f"(c[1]), "+f"(c[2]), "+f"(c[3])
        : "r"(a[0]), "r"(a[1]), "r"(a[2]), "r"(a[3]), "r"(b[0]), "r"(b[1]));
}
__device__ __forceinline__ void mma16816f(float* c, const uint32_t* a,
                                          const uint32_t* b) {
    asm volatile(
        "mma.sync.aligned.m16n8k16.row.col.f32.f16.f16.f32 "
        "{%0,%1,%2,%3}, {%4,%5,%6,%7}, {%8,%9}, {%0,%1,%2,%3};"
        : "+f"(c[0]), "+f"(c[1]), "+f"(c[2]), "+f"(c[3])
        : "r"(a[0]), "r"(a[1]), "r"(a[2]), "r"(a[3]), "r"(b[0]), "r"(b[1]));
}
#define CP_ASYNC16(dst_u32, src_ptr) \
    asm volatile("cp.async.cg.shared.global [%0], [%1], 16;" \
                 :: "r"(dst_u32), "l"(src_ptr))
#define CP_COMMIT() asm volatile("cp.async.commit_group;" ::: "memory")
#define CP_WAIT(N)  asm volatile("cp.async.wait_group %0;" :: "n"(N) : "memory")

// ---------------------------------------------------------------------------
// Kernel 0a: bf16 hi/lo split conversion of X and Wx^T. (unchanged)
// ---------------------------------------------------------------------------
__global__ void __launch_bounds__(256) conv_kernel(const float* __restrict__ x,
                                                   const float* __restrict__ W) {
    const size_t stride = (size_t)gridDim.x * blockDim.x;
    const size_t id0 = (size_t)blockIdx.x * blockDim.x + threadIdx.x;

    for (size_t i = id0; i < (size_t)TT * BB * DD; i += stride) {
        size_t m = i >> 9;
        int k = (int)(i & 511);
        int t = (int)(m >> 6);
        int r = (int)(m & 63);
        float v = x[(size_t)r * (TT * DD) + (size_t)t * DD + k];
        __nv_bfloat16 hi = __float2bfloat16(v);
        g_xhi[i] = hi;
        g_xlo[i] = __float2bfloat16(v - __bfloat162float(hi));
    }

    for (size_t i = id0; i < (size_t)NG * DD; i += stride) {
        int n = (int)(i & (NG - 1));
        int k = (int)(i >> 11);
        float v = W[(size_t)(HH + k) * NG + n];
        __nv_bfloat16 hi = __float2bfloat16(v);
        g_wthi[(size_t)n * DD + k] = hi;
        g_wtlo[(size_t)n * DD + k] = __float2bfloat16(v - __bfloat162float(hi));
    }
}

// ---------------------------------------------------------------------------
// Kernel 0b: per-replay state reset.
// ---------------------------------------------------------------------------
__global__ void __launch_bounds__(256) hinit_kernel() {
    int idx = blockIdx.x * blockDim.x + threadIdx.x;
    if (idx < NGRP * 32) g_bars[idx] = 0ULL;
    for (int i = idx; i < BB * HH; i += gridDim.x * blockDim.x)
        g_hf16[0][i] = __float2half(0.0f);
}

// ---------------------------------------------------------------------------
// Kernel 1: bf16 3-term split GEMM via mma.sync, cp.async double-buffered.
// (unchanged from R10/R12)
// ---------------------------------------------------------------------------
#define KP 40
#define XT (128 * KP)
#define XW_STAGE_B (4 * XT * 2)
#define XW_SMEM (2 * XW_STAGE_B)

__global__ void __launch_bounds__(256, 2) xw_mma(const float* __restrict__ bias) {
    extern __shared__ __align__(16) __nv_bfloat16 sbuf[];

    const int tid  = threadIdx.x;
    const int wid  = tid >> 5;
    const int lane = tid & 31;

    const int n0 = blockIdx.x * 128;
    const int m0 = blockIdx.y * 128;
    const int wm = (wid & 3) * 32;
    const int wn = (wid >> 2) * 64;

    const __nv_bfloat16* xh = g_xhi + (size_t)m0 * DD;
    const __nv_bfloat16* xl = g_xlo + (size_t)m0 * DD;
    const __nv_bfloat16* wh = g_wthi + (size_t)n0 * DD;
    const __nv_bfloat16* wl = g_wtlo + (size_t)n0 * DD;

    const uint32_t sb_u = smem_u32(sbuf);

    float cf[2][8][4];
#pragma unroll
    for (int mt = 0; mt < 2; ++mt)
#pragma unroll
        for (int nt = 0; nt < 8; ++nt)
#pragma unroll
            for (int i = 0; i < 4; ++i) cf[mt][nt][i] = 0.0f;

    const int srow = tid >> 2;
    const int sq   = (tid & 3) * 8;

    const int a_row = lane & 15;
    const int a_col = (lane >> 4) << 3;
    const int b_row = lane & 7;
    const int b_col = ((lane >> 3) & 1) << 3;

#define XW_ISSUE(K0, ST) do {                                                  \
        uint32_t sbase = sb_u + (uint32_t)(ST) * XW_STAGE_B;                   \
        _Pragma("unroll")                                                      \
        for (int i = 0; i < 2; ++i) {                                          \
            int row = srow + (i << 6);                                         \
            size_t go = (size_t)row * DD + (K0) + sq;                          \
            uint32_t so = sbase + (uint32_t)(row * KP + sq) * 2;               \
            CP_ASYNC16(so,              xh + go);                              \
            CP_ASYNC16(so + XT * 2,     xl + go);                              \
            CP_ASYNC16(so + 2 * XT * 2, wh + go);                              \
            CP_ASYNC16(so + 3 * XT * 2, wl + go);                              \
        }                                                                      \
        CP_COMMIT();                                                           \
    } while (0)

    XW_ISSUE(0, 0);

    for (int ci = 0; ci < 16; ++ci) {
        const int cur = ci & 1;
        if (ci < 15) {
            XW_ISSUE((ci + 1) * 32, cur ^ 1);
            CP_WAIT(1);
        } else {
            CP_WAIT(0);
        }
        __syncthreads();

        const uint32_t ah_u = sb_u + (uint32_t)cur * XW_STAGE_B;
        const uint32_t al_u = ah_u + XT * 2;
        const uint32_t bh_u = ah_u + 2 * XT * 2;
        const uint32_t bl_u = ah_u + 3 * XT * 2;

#pragma unroll
        for (int kk = 0; kk < 32; kk += 16) {
            uint32_t ah[2][4], al[2][4];
#pragma unroll
            for (int mt = 0; mt < 2; ++mt) {
                uint32_t off =
                    (uint32_t)(((wm + mt * 16 + a_row) * KP + kk + a_col) * 2);
                ldsm_x4(ah[mt][0], ah[mt][1], ah[mt][2], ah[mt][3], ah_u + off);
                ldsm_x4(al[mt][0], al[mt][1], al[mt][2], al[mt][3], al_u + off);
            }
#pragma unroll
            for (int nt = 0; nt < 8; ++nt) {
                uint32_t off =
                    (uint32_t)(((wn + nt * 8 + b_row) * KP + kk + b_col) * 2);
                uint32_t bh2[2], bl2[2];
                ldsm_x2(bh2[0], bh2[1], bh_u + off);
                ldsm_x2(bl2[0], bl2[1], bl_u + off);
#pragma unroll
                for (int mt = 0; mt < 2; ++mt) {
                    mma16816(cf[mt][nt], ah[mt], bh2);
                    mma16816(cf[mt][nt], ah[mt], bl2);
                    mma16816(cf[mt][nt], al[mt], bh2);
                }
            }
        }
        __syncthreads();
    }
#undef XW_ISSUE

    const int er = lane >> 2;
    const int ec = (lane & 3) << 1;
#pragma unroll
    for (int nt = 0; nt < 8; ++nt) {
        int coln = n0 + wn + nt * 8 + ec;
        float2 bv = *(const float2*)(bias + coln);
#pragma unroll
        for (int mt = 0; mt < 2; ++mt) {
            int rowm = m0 + wm + mt * 16 + er;
            float* d0 = g_xw + (size_t)rowm * NG + coln;
            float* d1 = g_xw + (size_t)(rowm + 8) * NG + coln;
            *(float2*)d0 = make_float2(cf[mt][nt][0] + bv.x, cf[mt][nt][1] + bv.y);
            *(float2*)d1 = make_float2(cf[mt][nt][2] + bv.x, cf[mt][nt][3] + bv.y);
        }
    }
}

// ---------------------------------------------------------------------------
// Kernel 2: persistent recurrent LSTM — fp16 h, single-fp16 W, W fragments
// register-resident (hoisted out of the t-loop). Per k16-step in the loop:
// 1 ldsm_x4 (h) + 1 HMMA. Counter barrier; out-store after arrive.
// ---------------------------------------------------------------------------
#define LSTM_SMEM ((16 + 64) * HP * 2 + 16 * 65 * 4 + 2 * 16 * 64 * 4 + 1024 + 512)

__global__ void __launch_bounds__(256, 1) lstm_rec(const float* __restrict__ W,
                                                   float* __restrict__ out) {
    extern __shared__ __align__(16) char smraw[];
    __half* shh = (__half*)smraw;                     // h fp16 [16][HP]
    __half* swh = shh + 16 * HP;                      // W_h fp16 [64][HP]
    float* sz   = (float*)(swh + 64 * HP);            // z tile [16][65]
    float* sxw  = sz + 16 * 65;                       // xw prefetch [2][16*64]
    float* shof = sxw + 2 * 16 * 64;                  // out f32 [16][16]
    __half* shout = (__half*)(shof + 256);            // h fp16 staging [256]

    const int tid  = threadIdx.x;
    const int lane = tid & 31;
    const int grp  = blockIdx.x >> 5;                 // batch group 0..3
    const int slot = blockIdx.x & 31;
    const int R0   = grp * ROWS_G;
    const int J0   = slot * JW;
    unsigned long long* bar = &g_bars[grp * 32];

    const uint32_t shh_u = smem_u32(shh);
    const uint32_t swh_u = smem_u32(swh);
    const uint32_t sxw_u = smem_u32(sxw);

    // xw prefetch ids: 16 rows x 64 local cols; 16B (4 floats) per thread
    const int xrow = tid >> 4;
    const int xn4  = tid & 15;
    const size_t xw_coloff = (size_t)((xn4 >> 2) << 9) + J0 + ((xn4 & 3) << 2);
    const uint32_t xw_soff = (uint32_t)(xrow * 64 + xn4 * 4) * 4;

    // Prologue: prefetch xw(t=0) into stage 0
    {
        const float* src = g_xw + ((size_t)(R0 + xrow)) * NG + xw_coloff;
        CP_ASYNC16(sxw_u + xw_soff, src);
        CP_COMMIT();
    }

    // Convert this CTA's W_h slice (64 gate cols) to single fp16 (once).
    for (int idx = tid; idx < GC * 512; idx += 256) {
        int n = idx & 63;
        int k = idx >> 6;
        float v = W[(size_t)k * NG + ((n >> 4) << 9) + J0 + (n & 15)];
        swh[n * HP + k] = __float2half(v);
    }

    const int n0w = (tid >> 5) * 8;                   // warp n-offset

    const int a_row = lane & 15;
    const int a_col = (lane >> 4) << 3;
    const int b_row = lane & 7;
    const int b_col = ((lane >> 3) & 1) << 3;

    const int er  = lane >> 2;
    const int ec2 = (lane & 3) << 1;
    const int gc  = n0w + ec2;

    const int gr = tid >> 4;
    const int gu = tid & 15;
    float cst = 0.0f;

    __syncthreads();

    // Hoist all 32 k-step W fragments into registers (loop-invariant over t)
    uint32_t wb[32][2];
#pragma unroll
    for (int ks = 0; ks < 32; ++ks) {
        uint32_t boff = (uint32_t)(((n0w + b_row) * HP + ks * 16 + b_col) * 2);
        ldsm_x2(wb[ks][0], wb[ks][1], swh_u + boff);
    }

    for (int t = 0; t < TT; ++t) {
        const __half* gh = g_hf16[t & 1] + (size_t)R0 * HH;

        // Issue h chunks c0, c1 (K halves of 256): 2 x 16B per thread each
#pragma unroll
        for (int cch = 0; cch < 2; ++cch) {
#pragma unroll
            for (int j = 0; j < 2; ++j) {
                int idx = tid + (j << 8);
                int row = idx >> 5;            // 0..15
                int seg = idx & 31;            // 32 x 8-elem segs
                int eoff = row * HP + cch * 256 + seg * 8;
                int goff = (row << 9) + cch * 256 + seg * 8;
                CP_ASYNC16(shh_u + eoff * 2, gh + goff);
            }
            CP_COMMIT();
        }
        // Prefetch xw(t+1)
        {
            int tn = (t + 1 < TT) ? t + 1 : TT - 1;
            const float* src =
                g_xw + ((size_t)tn * 64 + R0 + xrow) * NG + xw_coloff;
            CP_ASYNC16(sxw_u + ((((t + 1) & 1)) << 12) + xw_soff, src);
            CP_COMMIT();
        }

        // forces {xw(t), c0}; c1 + xw(t+1) may pend
        CP_WAIT(2);
        __syncthreads();

        // Accumulator init from smem xw stage
        const float* xs = sxw + ((t & 1) << 10) + er * 64 + gc;
        float2 x0 = *(const float2*)xs;
        float2 x1 = *(const float2*)(xs + 8 * 64);
        float cacc[4] = {x0.x, x0.y, x1.x, x1.y};

#define LSTM_CHUNK(CCH)                                                        \
        {                                                                      \
            _Pragma("unroll")                                                  \
            for (int ks8 = 0; ks8 < 16; ++ks8) {                               \
                uint32_t aoff = (uint32_t)((a_row * HP +                       \
                                 (CCH) * 256 + ks8 * 16 + a_col) * 2);         \
                uint32_t ah[4];                                                \
                ldsm_x4(ah[0], ah[1], ah[2], ah[3], shh_u + aoff);             \
                mma16816f(cacc, ah, wb[(CCH) * 16 + ks8]);                     \
            }                                                                  \
        }
        LSTM_CHUNK(0)
        CP_WAIT(1);          // forces c1 (xw(t+1) may pend)
        __syncthreads();
        LSTM_CHUNK(1)
#undef LSTM_CHUNK

        // z -> smem z tile [16][65]
        sz[er * 65 + gc]           = cacc[0];
        sz[er * 65 + gc + 1]       = cacc[1];
        sz[(er + 8) * 65 + gc]     = cacc[2];
        sz[(er + 8) * 65 + gc + 1] = cacc[3];
        __syncthreads();

        // Gate math: local cols [0..15]=f, [16..31]=i, [32..47]=o, [48..63]=c_bar
        float zf = sz[gr * 65 + gu];
        float zi = sz[gr * 65 + 16 + gu];
        float zo = sz[gr * 65 + 32 + gu];
        float zc = sz[gr * 65 + 48 + gu];
        cst = sigf(zf) * cst + sigf(zi) * zc;
        float h = sigf(zo) * cst;

        // Stage outputs for coalesced stores
        shof[gr * 16 + gu]  = h;
        shout[gr * 16 + gu] = __float2half(h);
        __syncthreads();

        // h state stores FIRST (they gate the other CTAs): 16 rows x 32B
        if (tid < 32) {
            int rr = tid >> 1, hf = tid & 1;
            *(uint4*)(g_hf16[(t + 1) & 1] + ((size_t)(R0 + rr) << 9) + J0 + hf * 8)
                = *(uint4*)&shout[rr * 16 + hf * 8];
        }
        __syncthreads();                   // h stores ordered before release

        if (tid == 0) bar_arrive_release(bar);

        // out-store: off the critical path (after arrive)
        if (tid >= 64 && tid < 128) {
            int i = tid - 64, rr = i >> 2, q = i & 3;
            *(float4*)(out + (size_t)(R0 + rr) * (TT * HH) + (size_t)t * HH +
                       J0 + q * 4) = *(float4*)&shof[rr * 16 + q * 4];
        }

        // Wait: single-counter poll
        if (tid == 0) {
            unsigned long long target = (unsigned long long)(t + 1) * GRP_CTAS;
            while (bar_ld_acquire(bar) < target) { }
        }
        __syncthreads();
    }
}

// ---------------------------------------------------------------------------
extern "C" void kernel_launch(void* const* d_in, const int* in_sizes, int n_in,
                              void* d_out, int out_size) {
    const float* x = (const float*)d_in[0];   // [64, 512, 512]
    const float* W = (const float*)d_in[1];   // [1024, 2048]
    const float* b = (const float*)d_in[2];   // [2048]
    float* out = (float*)d_out;               // [64, 512, 512]

    conv_kernel<<<1024, 256>>>(x, W);
    hinit_kernel<<<32, 256>>>();

    cudaFuncSetAttribute(xw_mma, cudaFuncAttributeMaxDynamicSharedMemorySize,
                         XW_SMEM);
    dim3 g1(NG / 128, (TT * BB) / 128);       // (16, 256)
    xw_mma<<<g1, 256, XW_SMEM>>>(b);

    cudaFuncSetAttribute(lstm_rec, cudaFuncAttributeMaxDynamicSharedMemorySize,
                         LSTM_SMEM);
    lstm_rec<<<GCTA, 256, LSTM_SMEM>>>(W, out);
}

// round 14
// speedup vs baseline: 1.7507x; 1.2472x over previous
#include <cuda_runtime.h>
#include <cuda_bf16.h>
#include <cuda_fp16.h>
#include <cstdint>
#include <math.h>

// Problem dims
#define BB 64
#define TT 512
#define DD 512
#define HH 512
#define NG 2048          // 4*H gate columns

// Recurrent partitioning: 128 CTAs = 4 batch-groups x 32 unit-CTAs
#define GCTA   128
#define NGRP   4
#define GRP_CTAS 32
#define ROWS_G 16        // batch rows per group
#define JW     16        // hidden units per CTA
#define GC     64        // gate cols per CTA
#define HP     520       // padded row stride (elements) for ldmatrix tiles

// ---------------------------------------------------------------------------
// Device scratch (allocation-free per harness rules)
// ---------------------------------------------------------------------------
__device__ float g_xw[(size_t)TT * BB * NG];          // [m=t*64+r][2048] fp32 (bias incl.)
__device__ unsigned long long g_bars[NGRP * 32];      // per-group counters, 256B apart
__device__ __half g_xf16[(size_t)TT * BB * DD];       // X fp16 [32768,512]
__device__ __half g_wtf16[(size_t)NG * DD];           // Wx^T fp16 [2048,512]
__device__ __half g_hf16[2][BB * HH];                 // h state fp16, [r][k], dbl-buf

__device__ __forceinline__ float sigf(float x) {
    return 1.0f / (1.0f + __expf(-x));
}

__device__ __forceinline__ uint32_t smem_u32(const void* p) {
    uint32_t a;
    asm("{ .reg .u64 t; cvta.to.shared.u64 t, %1; cvt.u32.u64 %0, t; }"
        : "=r"(a) : "l"(p));
    return a;
}

__device__ __forceinline__ void bar_arrive_release(unsigned long long* ctr) {
    asm volatile(
        "{ .reg .u64 a; cvta.to.global.u64 a, %0;"
        "  red.release.gpu.global.add.u64 [a], %1; }"
        :: "l"(ctr), "l"(1ULL) : "memory");
}
__device__ __forceinline__ unsigned long long bar_ld_acquire(
        unsigned long long* ctr) {
    unsigned long long v;
    asm volatile(
        "{ .reg .u64 a; cvta.to.global.u64 a, %1;"
        "  ld.acquire.gpu.global.u64 %0, [a]; }"
        : "=l"(v) : "l"(ctr) : "memory");
    return v;
}

// ---------------------------------------------------------------------------
// mma.sync / ldmatrix / cp.async helpers (baseline PTX, plain sm_103 target)
// ---------------------------------------------------------------------------
__device__ __forceinline__ void ldsm_x4(uint32_t& r0, uint32_t& r1,
                                        uint32_t& r2, uint32_t& r3,
                                        uint32_t addr) {
    asm volatile("ldmatrix.sync.aligned.m8n8.x4.shared.b16 {%0,%1,%2,%3}, [%4];"
                 : "=r"(r0), "=r"(r1), "=r"(r2), "=r"(r3) : "r"(addr));
}
__device__ __forceinline__ void ldsm_x2(uint32_t& r0, uint32_t& r1,
                                        uint32_t addr) {
    asm volatile("ldmatrix.sync.aligned.m8n8.x2.shared.b16 {%0,%1}, [%2];"
                 : "=r"(r0), "=r"(r1) : "r"(addr));
}
__device__ __forceinline__ void mma16816f(float* c, const uint32_t* a,
                                          const uint32_t* b) {
    asm volatile(
        "mma.sync.aligned.m16n8k16.row.col.f32.f16.f16.f32 "
        "{%0,%1,%2,%3}, {%4,%5,%6,%7}, {%8,%9}, {%0,%1,%2,%3};"
        : "+f"(c[0]), "+f"(c[1]), "+f"(c[2]), "+f"(c[3])
        : "r"(a[0]), "r"(a[1]), "r"(a[2]), "r"(a[3]), "r"(b[0]), "r"(b[1]));
}
#define CP_ASYNC16(dst_u32, src_ptr) \
    asm volatile("cp.async.cg.shared.global [%0], [%1], 16;" \
                 :: "r"(dst_u32), "l"(src_ptr))
#define CP_COMMIT() asm volatile("cp.async.commit_group;" ::: "memory")
#define CP_WAIT(N)  asm volatile("cp.async.wait_group %0;" :: "n"(N) : "memory")

// ---------------------------------------------------------------------------
// Kernel 0a: fp16 conversion of X and Wx^T.
// ---------------------------------------------------------------------------
__global__ void __launch_bounds__(256) conv_kernel(const float* __restrict__ x,
                                                   const float* __restrict__ W) {
    const size_t stride = (size_t)gridDim.x * blockDim.x;
    const size_t id0 = (size_t)blockIdx.x * blockDim.x + threadIdx.x;

    for (size_t i = id0; i < (size_t)TT * BB * DD; i += stride) {
        size_t m = i >> 9;
        int k = (int)(i & 511);
        int t = (int)(m >> 6);
        int r = (int)(m & 63);
        g_xf16[i] = __float2half(x[(size_t)r * (TT * DD) + (size_t)t * DD + k]);
    }

    for (size_t i = id0; i < (size_t)NG * DD; i += stride) {
        int n = (int)(i & (NG - 1));
        int k = (int)(i >> 11);
        g_wtf16[(size_t)n * DD + k] = __float2half(W[(size_t)(HH + k) * NG + n]);
    }
}

// ---------------------------------------------------------------------------
// Kernel 0b: per-replay state reset.
// ---------------------------------------------------------------------------
__global__ void __launch_bounds__(256) hinit_kernel() {
    int idx = blockIdx.x * blockDim.x + threadIdx.x;
    if (idx < NGRP * 32) g_bars[idx] = 0ULL;
    for (int i = idx; i < BB * HH; i += gridDim.x * blockDim.x)
        g_hf16[0][i] = __float2half(0.0f);
}

// ---------------------------------------------------------------------------
// Kernel 1: single-term fp16 GEMM via mma.sync, cp.async double-buffered.
// CTA tile 128x128, 8 warps (warp tile 32x64), K chunked x32, 2 stages.
// ---------------------------------------------------------------------------
#define KP 40
#define XT (128 * KP)
#define XW_STAGE_B (2 * XT * 2)   // 2 tiles (A, B) per stage
#define XW_SMEM (2 * XW_STAGE_B)

__global__ void __launch_bounds__(256, 2) xw_mma(const float* __restrict__ bias) {
    extern __shared__ __align__(16) __half sbuf[];

    const int tid  = threadIdx.x;
    const int wid  = tid >> 5;
    const int lane = tid & 31;

    const int n0 = blockIdx.x * 128;
    const int m0 = blockIdx.y * 128;
    const int wm = (wid & 3) * 32;
    const int wn = (wid >> 2) * 64;

    const __half* xa = g_xf16 + (size_t)m0 * DD;
    const __half* wb = g_wtf16 + (size_t)n0 * DD;

    const uint32_t sb_u = smem_u32(sbuf);

    float cf[2][8][4];
#pragma unroll
    for (int mt = 0; mt < 2; ++mt)
#pragma unroll
        for (int nt = 0; nt < 8; ++nt)
#pragma unroll
            for (int i = 0; i < 4; ++i) cf[mt][nt][i] = 0.0f;

    const int srow = tid >> 2;
    const int sq   = (tid & 3) * 8;

    const int a_row = lane & 15;
    const int a_col = (lane >> 4) << 3;
    const int b_row = lane & 7;
    const int b_col = ((lane >> 3) & 1) << 3;

#define XW_ISSUE(K0, ST) do {                                                  \
        uint32_t sbase = sb_u + (uint32_t)(ST) * XW_STAGE_B;                   \
        _Pragma("unroll")                                                      \
        for (int i = 0; i < 2; ++i) {                                          \
            int row = srow + (i << 6);                                         \
            size_t go = (size_t)row * DD + (K0) + sq;                          \
            uint32_t so = sbase + (uint32_t)(row * KP + sq) * 2;               \
            CP_ASYNC16(so,          xa + go);                                  \
            CP_ASYNC16(so + XT * 2, wb + go);                                  \
        }                                                                      \
        CP_COMMIT();                                                           \
    } while (0)

    XW_ISSUE(0, 0);

    for (int ci = 0; ci < 16; ++ci) {
        const int cur = ci & 1;
        if (ci < 15) {
            XW_ISSUE((ci + 1) * 32, cur ^ 1);
            CP_WAIT(1);
        } else {
            CP_WAIT(0);
        }
        __syncthreads();

        const uint32_t a_u = sb_u + (uint32_t)cur * XW_STAGE_B;
        const uint32_t b_u = a_u + XT * 2;

#pragma unroll
        for (int kk = 0; kk < 32; kk += 16) {
            uint32_t ah[2][4];
#pragma unroll
            for (int mt = 0; mt < 2; ++mt) {
                uint32_t off =
                    (uint32_t)(((wm + mt * 16 + a_row) * KP + kk + a_col) * 2);
                ldsm_x4(ah[mt][0], ah[mt][1], ah[mt][2], ah[mt][3], a_u + off);
            }
#pragma unroll
            for (int nt = 0; nt < 8; ++nt) {
                uint32_t off =
                    (uint32_t)(((wn + nt * 8 + b_row) * KP + kk + b_col) * 2);
                uint32_t b2[2];
                ldsm_x2(b2[0], b2[1], b_u + off);
#pragma unroll
                for (int mt = 0; mt < 2; ++mt)
                    mma16816f(cf[mt][nt], ah[mt], b2);
            }
        }
        __syncthreads();
    }
#undef XW_ISSUE

    const int er = lane >> 2;
    const int ec = (lane & 3) << 1;
#pragma unroll
    for (int nt = 0; nt < 8; ++nt) {
        int coln = n0 + wn + nt * 8 + ec;
        float2 bv = *(const float2*)(bias + coln);
#pragma unroll
        for (int mt = 0; mt < 2; ++mt) {
            int rowm = m0 + wm + mt * 16 + er;
            float* d0 = g_xw + (size_t)rowm * NG + coln;
            float* d1 = g_xw + (size_t)(rowm + 8) * NG + coln;
            *(float2*)d0 = make_float2(cf[mt][nt][0] + bv.x, cf[mt][nt][1] + bv.y);
            *(float2*)d1 = make_float2(cf[mt][nt][2] + bv.x, cf[mt][nt][3] + bv.y);
        }
    }
}

// ---------------------------------------------------------------------------
// Kernel 2: persistent recurrent LSTM — fp16 h, reg-resident W fragments,
// direct (unstaged) h/out stores from the gate threads.
// ---------------------------------------------------------------------------
#define LSTM_SMEM ((16 + 64) * HP * 2 + 16 * 65 * 4 + 2 * 16 * 64 * 4)

__global__ void __launch_bounds__(256, 1) lstm_rec(const float* __restrict__ W,
                                                   float* __restrict__ out) {
    extern __shared__ __align__(16) char smraw[];
    __half* shh = (__half*)smraw;                     // h fp16 [16][HP]
    __half* swh = shh + 16 * HP;                      // W_h fp16 [64][HP]
    float* sz   = (float*)(swh + 64 * HP);            // z tile [16][65]
    float* sxw  = sz + 16 * 65;                       // xw prefetch [2][16*64]

    const int tid  = threadIdx.x;
    const int lane = tid & 31;
    const int grp  = blockIdx.x >> 5;                 // batch group 0..3
    const int slot = blockIdx.x & 31;
    const int R0   = grp * ROWS_G;
    const int J0   = slot * JW;
    unsigned long long* bar = &g_bars[grp * 32];

    const uint32_t shh_u = smem_u32(shh);
    const uint32_t swh_u = smem_u32(swh);
    const uint32_t sxw_u = smem_u32(sxw);

    // xw prefetch ids: 16 rows x 64 local cols; 16B (4 floats) per thread
    const int xrow = tid >> 4;
    const int xn4  = tid & 15;
    const size_t xw_coloff = (size_t)((xn4 >> 2) << 9) + J0 + ((xn4 & 3) << 2);
    const uint32_t xw_soff = (uint32_t)(xrow * 64 + xn4 * 4) * 4;

    // Prologue: prefetch xw(t=0) into stage 0
    {
        const float* src = g_xw + ((size_t)(R0 + xrow)) * NG + xw_coloff;
        CP_ASYNC16(sxw_u + xw_soff, src);
        CP_COMMIT();
    }

    // Convert this CTA's W_h slice (64 gate cols) to single fp16 (once).
    for (int idx = tid; idx < GC * 512; idx += 256) {
        int n = idx & 63;
        int k = idx >> 6;
        float v = W[(size_t)k * NG + ((n >> 4) << 9) + J0 + (n & 15)];
        swh[n * HP + k] = __float2half(v);
    }

    const int n0w = (tid >> 5) * 8;                   // warp n-offset

    const int a_row = lane & 15;
    const int a_col = (lane >> 4) << 3;
    const int b_row = lane & 7;
    const int b_col = ((lane >> 3) & 1) << 3;

    const int er  = lane >> 2;
    const int ec2 = (lane & 3) << 1;
    const int gc  = n0w + ec2;

    const int gr = tid >> 4;
    const int gu = tid & 15;
    float cst = 0.0f;

    // Direct-store addresses for the gate thread (row gr, unit gu)
    __half* hst0 = g_hf16[0] + ((size_t)(R0 + gr) << 9) + J0 + gu;
    __half* hst1 = g_hf16[1] + ((size_t)(R0 + gr) << 9) + J0 + gu;
    float* outp  = out + (size_t)(R0 + gr) * (TT * HH) + J0 + gu;

    __syncthreads();

    // Hoist all 32 k-step W fragments into registers (loop-invariant over t)
    uint32_t wb[32][2];
#pragma unroll
    for (int ks = 0; ks < 32; ++ks) {
        uint32_t boff = (uint32_t)(((n0w + b_row) * HP + ks * 16 + b_col) * 2);
        ldsm_x2(wb[ks][0], wb[ks][1], swh_u + boff);
    }

    for (int t = 0; t < TT; ++t) {
        const __half* gh = g_hf16[t & 1] + (size_t)R0 * HH;

        // Issue h chunks c0, c1 (K halves of 256): 2 x 16B per thread each
#pragma unroll
        for (int cch = 0; cch < 2; ++cch) {
#pragma unroll
            for (int j = 0; j < 2; ++j) {
                int idx = tid + (j << 8);
                int row = idx >> 5;            // 0..15
                int seg = idx & 31;            // 32 x 8-elem segs
                int eoff = row * HP + cch * 256 + seg * 8;
                int goff = (row << 9) + cch * 256 + seg * 8;
                CP_ASYNC16(shh_u + eoff * 2, gh + goff);
            }
            CP_COMMIT();
        }
        // Prefetch xw(t+1)
        {
            int tn = (t + 1 < TT) ? t + 1 : TT - 1;
            const float* src =
                g_xw + ((size_t)tn * 64 + R0 + xrow) * NG + xw_coloff;
            CP_ASYNC16(sxw_u + ((((t + 1) & 1)) << 12) + xw_soff, src);
            CP_COMMIT();
        }

        // forces {xw(t), c0}; c1 + xw(t+1) may pend
        CP_WAIT(2);
        __syncthreads();

        // Accumulator init from smem xw stage
        const float* xs = sxw + ((t & 1) << 10) + er * 64 + gc;
        float2 x0 = *(const float2*)xs;
        float2 x1 = *(const float2*)(xs + 8 * 64);
        float cacc[4] = {x0.x, x0.y, x1.x, x1.y};

#define LSTM_CHUNK(CCH)                                                        \
        {                                                                      \
            _Pragma("unroll")                                                  \
            for (int ks8 = 0; ks8 < 16; ++ks8) {                               \
                uint32_t aoff = (uint32_t)((a_row * HP +                       \
                                 (CCH) * 256 + ks8 * 16 + a_col) * 2);         \
                uint32_t ah[4];                                                \
                ldsm_x4(ah[0], ah[1], ah[2], ah[3], shh_u + aoff);             \
                mma16816f(cacc, ah, wb[(CCH) * 16 + ks8]);                     \
            }                                                                  \
        }
        LSTM_CHUNK(0)
        CP_WAIT(1);          // forces c1 (xw(t+1) may pend)
        __syncthreads();
        LSTM_CHUNK(1)
#undef LSTM_CHUNK

        // z -> smem z tile [16][65]
        sz[er * 65 + gc]           = cacc[0];
        sz[er * 65 + gc + 1]       = cacc[1];
        sz[(er + 8) * 65 + gc]     = cacc[2];
        sz[(er + 8) * 65 + gc + 1] = cacc[3];
        __syncthreads();

        // Gate math: local cols [0..15]=f, [16..31]=i, [32..47]=o, [48..63]=c_bar
        float zf = sz[gr * 65 + gu];
        float zi = sz[gr * 65 + 16 + gu];
        float zo = sz[gr * 65 + 32 + gu];
        float zc = sz[gr * 65 + 48 + gu];
        cst = sigf(zf) * cst + sigf(zi) * zc;
        float h = sigf(zo) * cst;

        // Direct h state store (16 threads/row -> 32B sectors)
        *(((t + 1) & 1) ? hst1 : hst0) = __float2half(h);
        __syncthreads();                   // all h stores before release

        if (tid == 0) bar_arrive_release(bar);

        // out store: off the critical path (after arrive); 64B/row coalesced
        outp[(size_t)t * HH] = h;

        // Wait: single-counter poll
        if (tid == 0) {
            unsigned long long target = (unsigned long long)(t + 1) * GRP_CTAS;
            while (bar_ld_acquire(bar) < target) { }
        }
        __syncthreads();
    }
}

// ---------------------------------------------------------------------------
extern "C" void kernel_launch(void* const* d_in, const int* in_sizes, int n_in,
                              void* d_out, int out_size) {
    const float* x = (const float*)d_in[0];   // [64, 512, 512]
    const float* W = (const float*)d_in[1];   // [1024, 2048]
    const float* b = (const float*)d_in[2];   // [2048]
    float* out = (float*)d_out;               // [64, 512, 512]

    conv_kernel<<<1024, 256>>>(x, W);
    hinit_kernel<<<32, 256>>>();

    cudaFuncSetAttribute(xw_mma, cudaFuncAttributeMaxDynamicSharedMemorySize,
                         XW_SMEM);
    dim3 g1(NG / 128, (TT * BB) / 128);       // (16, 256)
    xw_mma<<<g1, 256, XW_SMEM>>>(b);

    cudaFuncSetAttribute(lstm_rec, cudaFuncAttributeMaxDynamicSharedMemorySize,
                         LSTM_SMEM);
    lstm_rec<<<GCTA, 256, LSTM_SMEM>>>(W, out);
}